// round 2
// baseline (speedup 1.0000x reference)
#include <cuda_runtime.h>
#include <cstdint>

#define NF 27           // 1 dense + 26 sparse
#define ND 128
#define NBATCH 16384
#define SSTRIDE 132     // smem row stride in floats (128 + 4 pad, stride/4 odd => conflict-free)
#define WPC 4           // warps per CTA
#define OUT_ROW 479     // 128 + 27*26/2

// packed 2x fp32 fma (Blackwell f32x2 pipe)
__device__ __forceinline__ unsigned long long fma2(unsigned long long a,
                                                   unsigned long long b,
                                                   unsigned long long c) {
    unsigned long long d;
    asm("fma.rn.f32x2 %0, %1, %2, %3;" : "=l"(d) : "l"(a), "l"(b), "l"(c));
    return d;
}

extern "C" __global__ void __launch_bounds__(WPC * 32, 4)
interaction_kernel(const float* __restrict__ dense,
                   const float* __restrict__ sparse,
                   float* __restrict__ out)
{
    extern __shared__ float smem[];                 // WPC * NF * SSTRIDE floats
    const int warp = threadIdx.x >> 5;
    const int lane = threadIdx.x & 31;
    float* sx = smem + warp * (NF * SSTRIDE);

    const int b = blockIdx.x * WPC + warp;          // grid*WPC == NBATCH exactly

    float* orow = out + (size_t)b * OUT_ROW;

    // ---- load dense row (combined row 0): 32 float4, one per lane; also passthrough to out
    const float4* dsrc = reinterpret_cast<const float4*>(dense + (size_t)b * ND);
    {
        float4 dv = dsrc[lane];
        *reinterpret_cast<float4*>(&sx[0 * SSTRIDE + lane * 4]) = dv;
        // out row base is only 4B aligned (479 floats/row) -> scalar stores
        orow[lane * 4 + 0] = dv.x;
        orow[lane * 4 + 1] = dv.y;
        orow[lane * 4 + 2] = dv.z;
        orow[lane * 4 + 3] = dv.w;
    }

    // ---- load 26 sparse rows (combined rows 1..26), fully coalesced float4
    const float4* ssrc = reinterpret_cast<const float4*>(sparse + (size_t)b * 26 * ND);
    #pragma unroll
    for (int f = 0; f < 26; ++f) {
        float4 v = ssrc[f * 32 + lane];
        *reinterpret_cast<float4*>(&sx[(f + 1) * SSTRIDE + lane * 4]) = v;
    }
    __syncwarp();   // warp-private smem region: warp sync + memfence is enough

    // ---- gram: lane j accumulates G[i][j] for all i (full square; triangle stored)
    unsigned long long acc[NF];
    #pragma unroll
    for (int i = 0; i < NF; ++i) acc[i] = 0ull;     // bit pattern {+0.f,+0.f}

    const int jrow = (lane < NF) ? lane : (NF - 1); // clamp idle lanes (never stored)
    const float* ownrow = sx + jrow * SSTRIDE;

    #pragma unroll 2
    for (int d = 0; d < ND; d += 4) {
        // own column operand: x[j][d..d+3] as two packed f32x2
        ulonglong2 own = *reinterpret_cast<const ulonglong2*>(ownrow + d);
        #pragma unroll
        for (int i = 0; i < NF; ++i) {
            // broadcast operand x[i][d..d+3] (uniform address -> smem broadcast)
            ulonglong2 bv = *reinterpret_cast<const ulonglong2*>(sx + i * SSTRIDE + d);
            acc[i] = fma2(bv.x, own.x, acc[i]);
            acc[i] = fma2(bv.y, own.y, acc[i]);
        }
    }

    // ---- epilogue: horizontal add of f32x2, store strict upper triangle
    // flat index of (i,j), i<j: p = 26*i - i*(i-1)/2 + (j-i-1)
    const int j = lane;
    #pragma unroll
    for (int i = 0; i < NF - 1; ++i) {
        float lo = __uint_as_float((unsigned)(acc[i] & 0xffffffffull));
        float hi = __uint_as_float((unsigned)(acc[i] >> 32));
        float v = lo + hi;
        if (j > i && j < NF) {
            int p = 26 * i - (i * (i - 1)) / 2 + (j - i - 1);
            orow[ND + p] = v;   // consecutive lanes -> consecutive addresses (coalesced)
        }
    }
}

extern "C" void kernel_launch(void* const* d_in, const int* in_sizes, int n_in,
                              void* d_out, int out_size)
{
    const float* dense  = (const float*)d_in[0];
    const float* sparse = (const float*)d_in[1];
    float* out = (float*)d_out;

    const int smem_bytes = WPC * NF * SSTRIDE * (int)sizeof(float);  // 57024
    cudaFuncSetAttribute(interaction_kernel,
                         cudaFuncAttributeMaxDynamicSharedMemorySize, smem_bytes);
    interaction_kernel<<<NBATCH / WPC, WPC * 32, smem_bytes>>>(dense, sparse, out);
}

// round 5
// speedup vs baseline: 1.1208x; 1.1208x over previous
#include <cuda_runtime.h>
#include <cstdint>

#define NF 27           // 1 dense + 26 sparse
#define ND 128
#define NBATCH 16384
#define WPC 4           // warps per CTA
#define OUT_ROW 479     // 128 + 27*26/2
#define SKEY(f) (((f) >> 2) & 7)   // per-row XOR swizzle key on 16B-chunk index

// packed 2x fp32 fma (Blackwell f32x2 pipe)
__device__ __forceinline__ unsigned long long fma2(unsigned long long a,
                                                   unsigned long long b,
                                                   unsigned long long c) {
    unsigned long long d;
    asm("fma.rn.f32x2 %0, %1, %2, %3;" : "=l"(d) : "l"(a), "l"(b), "l"(c));
    return d;
}

extern "C" __global__ void __launch_bounds__(WPC * 32, 4)
interaction_kernel(const float* __restrict__ dense,
                   const float* __restrict__ sparse,
                   float* __restrict__ out)
{
    extern __shared__ float smem[];                 // WPC * NF * ND floats, swizzled
    const int warp = threadIdx.x >> 5;
    const int lane = threadIdx.x & 31;
    float* sx = smem + warp * (NF * ND);

    const int b = blockIdx.x * WPC + warp;          // grid*WPC == NBATCH exactly
    float* orow = out + (size_t)b * OUT_ROW;

    // ---- load dense row (combined row 0); lane loads chunk c=lane; passthrough to out
    const float4* dsrc = reinterpret_cast<const float4*>(dense + (size_t)b * ND);
    {
        float4 dv = dsrc[lane];
        *reinterpret_cast<float4*>(&sx[(lane ^ SKEY(0)) << 2]) = dv;
        orow[lane * 4 + 0] = dv.x;                  // out row only 4B-aligned -> scalar
        orow[lane * 4 + 1] = dv.y;
        orow[lane * 4 + 2] = dv.z;
        orow[lane * 4 + 3] = dv.w;
    }

    // ---- load 26 sparse rows (combined rows 1..26), coalesced float4, swizzled store
    const float4* ssrc = reinterpret_cast<const float4*>(sparse + (size_t)b * 26 * ND);
    #pragma unroll
    for (int f = 0; f < 26; ++f) {
        const int row = f + 1;
        float4 v = ssrc[f * 32 + lane];
        *reinterpret_cast<float4*>(&sx[row * ND + ((lane ^ SKEY(row)) << 2)]) = v;
    }
    __syncwarp();   // warp-private smem region

    // ---- register-tiled gram: lane (rg,cg) computes rows rg*7+k (k<7), cols cg*4+m (m<4)
    const int rg = lane >> 3;                       // 0..3  -> 4*7 = 28 rows (27 used)
    const int cg = lane & 7;                        // 0..7  -> 8*4 = 32 cols (27 used)

    // precompute swizzled row base pointers + keys (clamp out-of-range to row 26)
    const float* abase[7];
    int akey[7];
    #pragma unroll
    for (int k = 0; k < 7; ++k) {
        int r = rg * 7 + k; if (r > 26) r = 26;
        abase[k] = sx + r * ND;
        akey[k] = SKEY(r);
    }
    const float* bbase[4];
    int bkey[4];
    #pragma unroll
    for (int m = 0; m < 4; ++m) {
        int cjj = cg * 4 + m; if (cjj > 26) cjj = 26;
        bbase[m] = sx + cjj * ND;
        bkey[m] = SKEY(cjj);
    }

    unsigned long long acc[7][4];                   // f32x2 accumulators
    #pragma unroll
    for (int k = 0; k < 7; ++k)
        #pragma unroll
        for (int m = 0; m < 4; ++m) acc[k][m] = 0ull;

    #pragma unroll 8
    for (int c = 0; c < 32; ++c) {                  // 16B chunks over d
        ulonglong2 av[7], bv[4];
        #pragma unroll
        for (int k = 0; k < 7; ++k)
            av[k] = *reinterpret_cast<const ulonglong2*>(abase[k] + ((c ^ akey[k]) << 2));
        #pragma unroll
        for (int m = 0; m < 4; ++m)
            bv[m] = *reinterpret_cast<const ulonglong2*>(bbase[m] + ((c ^ bkey[m]) << 2));
        #pragma unroll
        for (int k = 0; k < 7; ++k)
            #pragma unroll
            for (int m = 0; m < 4; ++m) {
                acc[k][m] = fma2(av[k].x, bv[m].x, acc[k][m]);
                acc[k][m] = fma2(av[k].y, bv[m].y, acc[k][m]);
            }
    }

    // ---- epilogue: horizontal add, store strict upper triangle
    // flat index of (i,j), i<j: p = 26*i - i*(i-1)/2 + (j-i-1)
    #pragma unroll
    for (int k = 0; k < 7; ++k) {
        const int i = rg * 7 + k;
        #pragma unroll
        for (int m = 0; m < 4; ++m) {
            const int j = cg * 4 + m;
            if (i < 27 && j < 27 && j > i) {
                float lo = __uint_as_float((unsigned)(acc[k][m] & 0xffffffffull));
                float hi = __uint_as_float((unsigned)(acc[k][m] >> 32));
                int p = 26 * i - (i * (i - 1)) / 2 + (j - i - 1);
                orow[ND + p] = lo + hi;
            }
        }
    }
}

extern "C" void kernel_launch(void* const* d_in, const int* in_sizes, int n_in,
                              void* d_out, int out_size)
{
    const float* dense  = (const float*)d_in[0];
    const float* sparse = (const float*)d_in[1];
    float* out = (float*)d_out;

    const int smem_bytes = WPC * NF * ND * (int)sizeof(float);  // 55296
    cudaFuncSetAttribute(interaction_kernel,
                         cudaFuncAttributeMaxDynamicSharedMemorySize, smem_bytes);
    interaction_kernel<<<NBATCH / WPC, WPC * 32, smem_bytes>>>(dense, sparse, out);
}

// round 6
// speedup vs baseline: 1.1395x; 1.0167x over previous
#include <cuda_runtime.h>
#include <cstdint>

#define NF 27            // 1 dense + 26 sparse
#define ND 128
#define NB 16384
#define RSTRIDE 132      // floats per feature row in smem (528B, 16B-aligned, bank-safe)
#define ROWSZ (NF * RSTRIDE)   // 3564 floats per batch row
#define WPC 4            // warps per CTA; each warp handles 2 batch rows
#define OUT_ROW 479      // 128 + 27*26/2

// packed 2x fp32 fma (Blackwell f32x2 pipe)
__device__ __forceinline__ unsigned long long fma2(unsigned long long a,
                                                   unsigned long long b,
                                                   unsigned long long c) {
    unsigned long long d;
    asm("fma.rn.f32x2 %0, %1, %2, %3;" : "=l"(d) : "l"(a), "l"(b), "l"(c));
    return d;
}

extern "C" __global__ void __launch_bounds__(WPC * 32, 2)
interaction_kernel(const float* __restrict__ dense,
                   const float* __restrict__ sparse,
                   float* __restrict__ out)
{
    extern __shared__ float smem[];               // WPC * 2 * ROWSZ floats
    const int warp = threadIdx.x >> 5;
    const int lane = threadIdx.x & 31;
    float* wbase = smem + warp * (2 * ROWSZ);

    const int b0 = (blockIdx.x * WPC + warp) * 2; // this warp's two batch rows

    // ---- fill smem (both rows, whole warp), plus dense passthrough to out
    #pragma unroll
    for (int h = 0; h < 2; ++h) {
        const int b = b0 + h;
        float* rb = wbase + h * ROWSZ;
        float* orow = out + (size_t)b * OUT_ROW;

        float4 dv = *reinterpret_cast<const float4*>(dense + (size_t)b * ND + lane * 4);
        *reinterpret_cast<float4*>(rb + lane * 4) = dv;     // feature 0
        orow[lane * 4 + 0] = dv.x;                          // out row only 4B-aligned
        orow[lane * 4 + 1] = dv.y;
        orow[lane * 4 + 2] = dv.z;
        orow[lane * 4 + 3] = dv.w;

        const float4* ssrc =
            reinterpret_cast<const float4*>(sparse + (size_t)b * 26 * ND);
        #pragma unroll
        for (int f = 0; f < 26; ++f) {
            float4 v = ssrc[f * 32 + lane];
            *reinterpret_cast<float4*>(rb + (f + 1) * RSTRIDE + lane * 4) = v;
        }
    }
    __syncwarp();

    // ---- register-tiled gram: half-warp h owns batch row b0+h
    // within 16 lanes: rg=(lane>>2)&3 -> rows rg*7+k, cg=lane&3 -> cols cg*7+m
    const int h  = lane >> 4;
    const int rg = (lane >> 2) & 3;
    const int cg = lane & 3;
    const float* sx = wbase + h * ROWSZ;

    const float* aptr[7];
    const float* bptr[7];
    #pragma unroll
    for (int k = 0; k < 7; ++k) {
        int r = rg * 7 + k; if (r > 26) r = 26;
        aptr[k] = sx + r * RSTRIDE;
    }
    #pragma unroll
    for (int m = 0; m < 7; ++m) {
        int j = cg * 7 + m; if (j > 26) j = 26;
        bptr[m] = sx + j * RSTRIDE;
    }

    unsigned long long acc[7][7];                 // f32x2 accumulators
    #pragma unroll
    for (int k = 0; k < 7; ++k)
        #pragma unroll
        for (int m = 0; m < 7; ++m) acc[k][m] = 0ull;

    #pragma unroll 2
    for (int c = 0; c < 32; ++c) {                // 16B chunks over d (affine addrs)
        ulonglong2 av[7], bv[7];
        #pragma unroll
        for (int k = 0; k < 7; ++k)
            av[k] = *reinterpret_cast<const ulonglong2*>(aptr[k] + c * 4);
        #pragma unroll
        for (int m = 0; m < 7; ++m)
            bv[m] = *reinterpret_cast<const ulonglong2*>(bptr[m] + c * 4);
        #pragma unroll
        for (int k = 0; k < 7; ++k)
            #pragma unroll
            for (int m = 0; m < 7; ++m) {
                acc[k][m] = fma2(av[k].x, bv[m].x, acc[k][m]);
                acc[k][m] = fma2(av[k].y, bv[m].y, acc[k][m]);
            }
    }

    // ---- epilogue: horizontal add, store strict upper triangle of own row
    // flat index of (i,j), i<j: p = 26*i - i*(i-1)/2 + (j-i-1)
    float* orow = out + (size_t)(b0 + h) * OUT_ROW;
    #pragma unroll
    for (int k = 0; k < 7; ++k) {
        const int i = rg * 7 + k;
        #pragma unroll
        for (int m = 0; m < 7; ++m) {
            const int j = cg * 7 + m;
            if (i < 27 && j < 27 && j > i) {
                float lo = __uint_as_float((unsigned)(acc[k][m] & 0xffffffffull));
                float hi = __uint_as_float((unsigned)(acc[k][m] >> 32));
                int p = 26 * i - (i * (i - 1)) / 2 + (j - i - 1);
                orow[ND + p] = lo + hi;
            }
        }
    }
}

extern "C" void kernel_launch(void* const* d_in, const int* in_sizes, int n_in,
                              void* d_out, int out_size)
{
    const float* dense  = (const float*)d_in[0];
    const float* sparse = (const float*)d_in[1];
    float* out = (float*)d_out;

    const int smem_bytes = WPC * 2 * ROWSZ * (int)sizeof(float);  // 114048
    cudaFuncSetAttribute(interaction_kernel,
                         cudaFuncAttributeMaxDynamicSharedMemorySize, smem_bytes);
    interaction_kernel<<<NB / (WPC * 2), WPC * 32, smem_bytes>>>(dense, sparse, out);
}

// round 8
// speedup vs baseline: 1.2196x; 1.0703x over previous
#include <cuda_runtime.h>
#include <cstdint>

#define NF 27            // 1 dense + 26 sparse
#define ND 128
#define NB 16384
#define RSTRIDE 132      // floats per feature row in smem (528B; conflict-free, see notes)
#define ROWSZ (NF * RSTRIDE)   // 3564 floats per batch row (14256 B)
#define WPC 4            // warps per CTA; 1 batch row per warp; 4 CTAs/SM -> 16 warps/SM
#define OUT_ROW 479      // 128 + 27*26/2

// packed 2x fp32 fma (Blackwell f32x2 pipe)
__device__ __forceinline__ unsigned long long fma2(unsigned long long a,
                                                   unsigned long long b,
                                                   unsigned long long c) {
    unsigned long long d;
    asm("fma.rn.f32x2 %0, %1, %2, %3;" : "=l"(d) : "l"(a), "l"(b), "l"(c));
    return d;
}

extern "C" __global__ void __launch_bounds__(WPC * 32, 4)
interaction_kernel(const float* __restrict__ dense,
                   const float* __restrict__ sparse,
                   float* __restrict__ out)
{
    extern __shared__ float smem[];               // WPC * ROWSZ floats
    const int warp = threadIdx.x >> 5;
    const int lane = threadIdx.x & 31;
    float* sx = smem + warp * ROWSZ;

    const int b = blockIdx.x * WPC + warp;        // grid*WPC == NB exactly
    float* orow = out + (size_t)b * OUT_ROW;

    // ---- fill smem: feature 0 = dense (plus passthrough), 1..26 = sparse
    {
        float4 dv = *reinterpret_cast<const float4*>(dense + (size_t)b * ND + lane * 4);
        *reinterpret_cast<float4*>(sx + lane * 4) = dv;
        orow[lane * 4 + 0] = dv.x;                // out row only 4B-aligned -> scalar
        orow[lane * 4 + 1] = dv.y;
        orow[lane * 4 + 2] = dv.z;
        orow[lane * 4 + 3] = dv.w;
    }
    const float4* ssrc = reinterpret_cast<const float4*>(sparse + (size_t)b * 26 * ND);
    #pragma unroll
    for (int f = 0; f < 26; ++f) {
        float4 v = ssrc[f * 32 + lane];           // 27 LDG.128 in flight (high MLP)
        *reinterpret_cast<float4*>(sx + (f + 1) * RSTRIDE + lane * 4) = v;
    }
    __syncwarp();                                 // warp-private smem region

    // ---- register-tiled gram
    // lane grid: rg = lane>>3 (4 groups), cg = lane&7 (8 groups)
    // lane computes rows i = rg*7+k (k<7), cols j = cg + 8*m (m<4)
    // bank check (stride 132 => row offset 16*r mod 128):
    //   a-load k: rows {k, k+7, k+14, k+21} -> slots {16k, +112, +96, +80}  distinct
    //   b-load m: rows {8m .. 8m+7}         -> slots {0,16,...,112}         distinct
    const int rg = lane >> 3;
    const int cg = lane & 7;

    const float* aptr[7];
    const float* bptr[4];
    #pragma unroll
    for (int k = 0; k < 7; ++k) {
        int r = rg * 7 + k; if (r > 26) r = 26;   // rg=3,k=6 -> 27: clamp (never stored)
        aptr[k] = sx + r * RSTRIDE;
    }
    #pragma unroll
    for (int m = 0; m < 4; ++m) {
        int j = cg + 8 * m; if (j > 26) j = 26;   // j in {27..31}: clamp (never stored)
        bptr[m] = sx + j * RSTRIDE;
    }

    unsigned long long acc[7][4];                 // f32x2 accumulators
    #pragma unroll
    for (int k = 0; k < 7; ++k)
        #pragma unroll
        for (int m = 0; m < 4; ++m) acc[k][m] = 0ull;

    #pragma unroll 4
    for (int c = 0; c < 32; ++c) {                // 16B chunks; addresses are [Rptr+imm]
        ulonglong2 av[7], bv[4];
        #pragma unroll
        for (int k = 0; k < 7; ++k)
            av[k] = *reinterpret_cast<const ulonglong2*>(aptr[k] + c * 4);
        #pragma unroll
        for (int m = 0; m < 4; ++m)
            bv[m] = *reinterpret_cast<const ulonglong2*>(bptr[m] + c * 4);
        #pragma unroll
        for (int k = 0; k < 7; ++k)
            #pragma unroll
            for (int m = 0; m < 4; ++m) {
                acc[k][m] = fma2(av[k].x, bv[m].x, acc[k][m]);
                acc[k][m] = fma2(av[k].y, bv[m].y, acc[k][m]);
            }
    }

    // ---- epilogue: horizontal add, store strict upper triangle
    // flat index of (i,j), i<j: p = 26*i - i*(i-1)/2 + (j-i-1)
    #pragma unroll
    for (int k = 0; k < 7; ++k) {
        const int i = rg * 7 + k;
        #pragma unroll
        for (int m = 0; m < 4; ++m) {
            const int j = cg + 8 * m;
            if (i < 27 && j < 27 && j > i) {
                float lo = __uint_as_float((unsigned)(acc[k][m] & 0xffffffffull));
                float hi = __uint_as_float((unsigned)(acc[k][m] >> 32));
                int p = 26 * i - (i * (i - 1)) / 2 + (j - i - 1);
                orow[ND + p] = lo + hi;
            }
        }
    }
}

extern "C" void kernel_launch(void* const* d_in, const int* in_sizes, int n_in,
                              void* d_out, int out_size)
{
    const float* dense  = (const float*)d_in[0];
    const float* sparse = (const float*)d_in[1];
    float* out = (float*)d_out;

    const int smem_bytes = WPC * ROWSZ * (int)sizeof(float);  // 57024
    cudaFuncSetAttribute(interaction_kernel,
                         cudaFuncAttributeMaxDynamicSharedMemorySize, smem_bytes);
    interaction_kernel<<<NB / WPC, WPC * 32, smem_bytes>>>(dense, sparse, out);
}